// round 7
// baseline (speedup 1.0000x reference)
#include <cuda_runtime.h>
#include <cstdint>

// Shapes fixed by the reference
#define BB 16
#define TT 8192
#define CC 512
#define YY 256
#define C4 (CC / 4)            // 128 float4 lanes per frame row
#define NSPAN (BB * YY)        // 4096
#define QFRAMES 16             // frames per work item (cnt < 64 -> <= 4 quarters)
#define MAXITEMS (NSPAN * 4)   // 16384
#define GRID_POOL (148 * 8)    // persistent pool blocks (R3-proven config)

// Scratch + scheduling state (allocation-free __device__ globals).
// g_next/g_nitems/g_done are self-restoring each launch (graph-replay safe).
__device__ int4 g_meta[NSPAN];         // {start, cnt, bits(1/cnt), 0}
__device__ int  g_items[MAXITEMS];     // packed (span<<2 | quarter), compacted
__device__ int  g_nitems = 0;
__device__ int  g_next   = GRID_POOL;
__device__ int  g_done   = 0;

// ---------------------------------------------------------------------------
// Setup kernel. grid = BB blocks, 256 threads (one per span of this batch):
//   1. Hillis-Steele cumsum of durations -> clamped (start, cnt, 1/cnt)
//   2. warp-aggregated compaction of non-empty quarter items (memory order)
//   3. zero the output (required: empty spans must be exact zeros, and the
//      pool kernel accumulates with global reductions)
// ---------------------------------------------------------------------------
__global__ void __launch_bounds__(YY) setup_kernel(const int* __restrict__ dur,
                                                   float* __restrict__ out) {
    __shared__ int s[YY];
    const int b = blockIdx.x;
    const int y = threadIdx.x;
    const int v = dur[b * YY + y];
    s[y] = v;
    __syncthreads();
    #pragma unroll
    for (int off = 1; off < YY; off <<= 1) {
        int add = (y >= off) ? s[y - off] : 0;
        __syncthreads();
        s[y] += add;
        __syncthreads();
    }
    const int incl = s[y];
    const int excl = incl - v;
    const int st  = min(excl, TT);
    const int en  = min(incl, TT);
    const int cnt = en - st;
    const float inv = (cnt > 0) ? (1.0f / (float)cnt) : 0.0f;
    const int by = b * YY + y;
    g_meta[by] = make_int4(st, cnt, __float_as_int(inv), 0);

    // ---- compact non-empty quarter items, warp-aggregated append ----
    const int nq = (cnt + QFRAMES - 1) / QFRAMES;   // 0..4
    const int lane = y & 31;
    int incl_nq = nq;
    #pragma unroll
    for (int o = 1; o < 32; o <<= 1) {
        int t = __shfl_up_sync(0xffffffffu, incl_nq, o);
        if (lane >= o) incl_nq += t;
    }
    const int warp_total = __shfl_sync(0xffffffffu, incl_nq, 31);
    const int excl_nq = incl_nq - nq;
    int base = 0;
    if (lane == 0) base = atomicAdd(&g_nitems, warp_total);
    base = __shfl_sync(0xffffffffu, base, 0);
    for (int k = 0; k < nq; k++)
        g_items[base + excl_nq + k] = (by << 2) | k;

    // ---- zero output (grid-stride over 512K float4 with 4096 threads) ----
    float4* o4 = reinterpret_cast<float4*>(out);
    const float4 z = make_float4(0.f, 0.f, 0.f, 0.f);
    for (int i = by; i < NSPAN * C4; i += NSPAN) o4[i] = z;
}

// ---------------------------------------------------------------------------
// Pool kernel: persistent blocks steal quarter-span items.
// 128 threads, one float4 channel lane each -> contiguous 2048B per frame
// row; unroll-4 with 4 independent accumulators (R3-proven streaming loop).
// Partial (pre-scaled by 1/cnt) is combined via red.global.add.v4.f32 —
// output is L2-resident, so the RMW never touches DRAM.
// ---------------------------------------------------------------------------
__global__ void __launch_bounds__(128, 8)
pool_kernel(const float* __restrict__ emg, float* __restrict__ out) {
    __shared__ int sh_next;
    const int tid = threadIdx.x;          // 0..127
    const int nitems = g_nitems;          // stable during this kernel

    int w = blockIdx.x;
    while (w < nitems) {
        // prefetch next item id (atomic latency hidden under the frame loop)
        if (tid == 0) sh_next = atomicAdd(&g_next, 1);

        const int item = g_items[w];      // uniform address -> broadcast
        const int by = item >> 2;
        const int q  = item & 3;
        const int4 m = __ldg(&g_meta[by]);
        const int b  = by >> 8;           // YY == 256
        const int f0 = q * QFRAMES;
        const int n  = min(m.y - f0, QFRAMES);   // >= 1 by construction
        const float inv = __int_as_float(m.z);

        const float4* p = reinterpret_cast<const float4*>(emg)
                          + ((size_t)b * TT + m.x + f0) * C4 + tid;

        float4 a0 = make_float4(0.f, 0.f, 0.f, 0.f);
        float4 a1 = a0, a2 = a0, a3 = a0;

        int t = 0;
        for (; t + 4 <= n; t += 4) {
            const float4 v0 = p[0 * C4];
            const float4 v1 = p[1 * C4];
            const float4 v2 = p[2 * C4];
            const float4 v3 = p[3 * C4];
            a0.x += v0.x; a0.y += v0.y; a0.z += v0.z; a0.w += v0.w;
            a1.x += v1.x; a1.y += v1.y; a1.z += v1.z; a1.w += v1.w;
            a2.x += v2.x; a2.y += v2.y; a2.z += v2.z; a2.w += v2.w;
            a3.x += v3.x; a3.y += v3.y; a3.z += v3.z; a3.w += v3.w;
            p += 4 * C4;
        }
        for (; t < n; t++) {
            const float4 vv = p[0];
            a0.x += vv.x; a0.y += vv.y; a0.z += vv.z; a0.w += vv.w;
            p += C4;
        }

        float4 r;
        r.x = ((a0.x + a1.x) + (a2.x + a3.x)) * inv;
        r.y = ((a0.y + a1.y) + (a2.y + a3.y)) * inv;
        r.z = ((a0.z + a1.z) + (a2.z + a3.z)) * inv;
        r.w = ((a0.w + a1.w) + (a2.w + a3.w)) * inv;

        float* dst = out + (size_t)by * CC + tid * 4;
        asm volatile("red.global.add.v4.f32 [%0], {%1, %2, %3, %4};"
                     :: "l"(dst), "f"(r.x), "f"(r.y), "f"(r.z), "f"(r.w)
                     : "memory");

        __syncthreads();
        w = sh_next;
        __syncthreads();
    }

    // last block restores scheduling state for the next (graph) launch
    if (tid == 0) {
        const int d = atomicAdd(&g_done, 1);
        if (d == GRID_POOL - 1) {
            g_nitems = 0;
            g_next   = GRID_POOL;
            g_done   = 0;
            __threadfence();
        }
    }
}

extern "C" void kernel_launch(void* const* d_in, const int* in_sizes, int n_in,
                              void* d_out, int out_size) {
    const float* emg = (const float*)d_in[0];
    const int*   dur = (const int*)d_in[1];
    float*       out = (float*)d_out;

    setup_kernel<<<BB, YY>>>(dur, out);
    pool_kernel<<<GRID_POOL, 128>>>(emg, out);
}

// round 8
// speedup vs baseline: 1.2315x; 1.2315x over previous
#include <cuda_runtime.h>

// Shapes fixed by the reference
#define BB 16
#define TT 8192
#define CC 512
#define YY 256
#define C4 (CC / 4)            // 128 float4 lanes per frame row
#define NSPAN (BB * YY)        // 4096
#define GRID_POOL (148 * 8)    // persistent pool blocks (R3-proven config)
#define BIG_THRESH 32          // LPT bucket threshold (frames)

// Scheduling state (allocation-free __device__ globals, self-restoring).
__device__ int g_items[NSPAN];         // span ids, big spans first
__device__ int g_front = 0;            // big-bucket cursor
__device__ int g_back  = NSPAN - 1;    // small-bucket cursor
__device__ int g_next  = GRID_POOL;    // steal cursor
__device__ int g_done  = 0;

// ---------------------------------------------------------------------------
// Kernel A (tiny): LPT placement. Spans with dur >= BIG_THRESH go to the
// front of the work queue, the rest to the back. Order within a bucket is
// race-dependent but each span is wholly owned by one pool block with
// sequential accumulation, so d_out is bitwise deterministic.
// ---------------------------------------------------------------------------
__global__ void __launch_bounds__(YY) place_kernel(const int* __restrict__ dur) {
    const int by = blockIdx.x * YY + threadIdx.x;
    const int d  = dur[by];
    int pos;
    if (d >= BIG_THRESH) pos = atomicAdd(&g_front, 1);
    else                 pos = atomicSub(&g_back, 1);
    g_items[pos] = by;
}

// ---------------------------------------------------------------------------
// Kernel B: persistent pool. Each block steals whole spans in LPT order.
// Per span:
//   0. thread 0 prefetches the NEXT item index (atomic hidden under loop)
//   1. threads 0..63 reduce durations[b,0..y-1] -> start; dur[b,y] -> cnt
//   2. 128 threads, one float4 channel lane each -> contiguous 2048B per
//      frame row; unroll-4 with 4 independent accumulators (R3-proven,
//      natural ~64 regs, 8 blocks/SM). DO NOT TOUCH THIS LOOP.
// Last block restores all scheduling state (graph-replay safe).
// ---------------------------------------------------------------------------
__global__ void __launch_bounds__(128, 8)
pool_kernel(const float* __restrict__ emg,
            const int*   __restrict__ dur,
            float*       __restrict__ out) {
    __shared__ int sh[4];            // [0],[1] warp sums, [2] cnt, [3] next idx
    const int tid = threadIdx.x;     // 0..127

    int w = blockIdx.x;
    while (w < NSPAN) {
        // ---- prefetch next work index ----
        if (tid == 0) sh[3] = atomicAdd(&g_next, 1);

        const int by = g_items[w];   // uniform -> broadcast
        const int b  = by >> 8;      // YY == 256
        const int y  = by & 255;

        // ---- span metadata: start = sum_{j<y} dur[b,j], cnt = dur[b,y] ----
        if (tid < 64) {
            const int4 v = __ldg(reinterpret_cast<const int4*>(dur) + b * 64 + tid);
            const int base = tid * 4;
            int s = 0;
            if (base + 0 < y) s += v.x;
            if (base + 1 < y) s += v.y;
            if (base + 2 < y) s += v.z;
            if (base + 3 < y) s += v.w;
            if ((y >> 2) == tid) {
                int c;
                switch (y & 3) {
                    case 0:  c = v.x; break;
                    case 1:  c = v.y; break;
                    case 2:  c = v.z; break;
                    default: c = v.w; break;
                }
                sh[2] = c;
            }
            #pragma unroll
            for (int o = 16; o; o >>= 1) s += __shfl_down_sync(0xffffffffu, s, o);
            if ((tid & 31) == 0) sh[tid >> 5] = s;
        }
        __syncthreads();

        const int start_raw = sh[0] + sh[1];
        const int st  = min(start_raw, TT);
        const int en  = min(start_raw + sh[2], TT);
        const int cnt = en - st;

        // ---- mean-pool cnt frames (R3 loop: unroll-4, 4 accumulators) ----
        const float4* p = reinterpret_cast<const float4*>(emg)
                          + ((size_t)b * TT + st) * C4 + tid;

        float4 a0 = make_float4(0.f, 0.f, 0.f, 0.f);
        float4 a1 = a0, a2 = a0, a3 = a0;

        int t = 0;
        for (; t + 4 <= cnt; t += 4) {
            const float4 v0 = p[0 * C4];
            const float4 v1 = p[1 * C4];
            const float4 v2 = p[2 * C4];
            const float4 v3 = p[3 * C4];
            a0.x += v0.x; a0.y += v0.y; a0.z += v0.z; a0.w += v0.w;
            a1.x += v1.x; a1.y += v1.y; a1.z += v1.z; a1.w += v1.w;
            a2.x += v2.x; a2.y += v2.y; a2.z += v2.z; a2.w += v2.w;
            a3.x += v3.x; a3.y += v3.y; a3.z += v3.z; a3.w += v3.w;
            p += 4 * C4;
        }
        for (; t < cnt; t++) {
            const float4 vv = p[0];
            a0.x += vv.x; a0.y += vv.y; a0.z += vv.z; a0.w += vv.w;
            p += C4;
        }

        const float inv = (cnt > 0) ? (1.0f / (float)cnt) : 0.0f;
        float4 r;
        r.x = ((a0.x + a1.x) + (a2.x + a3.x)) * inv;
        r.y = ((a0.y + a1.y) + (a2.y + a3.y)) * inv;
        r.z = ((a0.z + a1.z) + (a2.z + a3.z)) * inv;
        r.w = ((a0.w + a1.w) + (a2.w + a3.w)) * inv;

        reinterpret_cast<float4*>(out)[(size_t)by * C4 + tid] = r;

        // ---- consume prefetched work index ----
        __syncthreads();
        w = sh[3];
        __syncthreads();
    }

    // ---- last block restores scheduling state for the next replay ----
    if (tid == 0) {
        const int d = atomicAdd(&g_done, 1);
        if (d == GRID_POOL - 1) {
            g_front = 0;
            g_back  = NSPAN - 1;
            g_next  = GRID_POOL;
            g_done  = 0;
            __threadfence();
        }
    }
}

extern "C" void kernel_launch(void* const* d_in, const int* in_sizes, int n_in,
                              void* d_out, int out_size) {
    const float* emg = (const float*)d_in[0];
    const int*   dur = (const int*)d_in[1];
    float*       out = (float*)d_out;

    place_kernel<<<BB, YY>>>(dur);
    pool_kernel<<<GRID_POOL, 128>>>(emg, dur, out);
}